// round 10
// baseline (speedup 1.0000x reference)
#include <cuda_runtime.h>
#include <cstdint>

// x:      (16, 16, 64, 512)  f32
// kernel: (32, 16, 4)        f32
// points: (16, 3, 64, 512)   f32
// out:    (16, 32, 62, 510)  f32
#define CH_STRIDE 32768
#define HP 62
#define WP 510
#define OUT_PLANE (62*510)
#define DSTR 132                // epilogue smem stride (words)

typedef unsigned long long u64;
typedef unsigned int u32;

// K weights, tf32, fragment-ordered: Kfrag[o*64 + kt*8 + pos],
// pos = 2*(cl&3) + (cl>>2)  (pairs (cq, cq+4) adjacent -> LDG.64 fragments)
__device__ __align__(16) u32 Kfrag[2048];

__device__ __forceinline__ u64 pk(float lo, float hi) {
    u64 r; asm("mov.b64 %0, {%1,%2};" : "=l"(r) : "f"(lo), "f"(hi)); return r;
}
__device__ __forceinline__ void upk(u64 v, float& lo, float& hi) {
    asm("mov.b64 {%0,%1}, %2;" : "=f"(lo), "=f"(hi) : "l"(v));
}
__device__ __forceinline__ u64 fma2(u64 a, u64 b, u64 c) {
    u64 d; asm("fma.rn.f32x2 %0, %1, %2, %3;" : "=l"(d) : "l"(a), "l"(b), "l"(c)); return d;
}
__device__ __forceinline__ u64 add2(u64 a, u64 b) {
    u64 d; asm("add.rn.f32x2 %0, %1, %2;" : "=l"(d) : "l"(a), "l"(b)); return d;
}
__device__ __forceinline__ u64 neg2(u64 a) { return a ^ 0x8000000080000000ULL; }

__device__ __forceinline__ u32 tf32r(float f) {
    u32 r; asm("cvt.rna.tf32.f32 %0, %1;" : "=r"(r) : "f"(f)); return r;
}

__device__ __forceinline__ void mma_tf32(float& d0, float& d1, float& d2, float& d3,
                                         u32 a0, u32 a1, u32 a2, u32 a3,
                                         u32 b0, u32 b1) {
    asm volatile("mma.sync.aligned.m16n8k8.row.col.f32.tf32.tf32.f32 "
                 "{%0,%1,%2,%3}, {%4,%5,%6,%7}, {%8,%9}, {%0,%1,%2,%3};"
                 : "+f"(d0), "+f"(d1), "+f"(d2), "+f"(d3)
                 : "r"(a0), "r"(a1), "r"(a2), "r"(a3), "r"(b0), "r"(b1));
}

__global__ void prep_kfrag_kernel(const float* __restrict__ kern) {
    int idx = blockIdx.x * 256 + threadIdx.x;   // 0..2047 = o*64 + c
    int c  = idx & 63;
    int kt = c >> 3, cl = c & 7;
    int pos = 2 * (cl & 3) + (cl >> 2);
    Kfrag[(idx & ~63) + kt * 8 + pos] = tf32r(kern[idx]);
}

__global__ void __launch_bounds__(128, 6)
flex_conv_mma6_kernel(const float* __restrict__ x,
                      const float* __restrict__ pts,
                      float* __restrict__ out)
{
    // C tile: 128 px rows x 64 words. Within each row, 8 groups of 8 words;
    // group index swizzled: grp' = pr ^ (row & 7). Within a group, channel-lo /
    // channel-hi values interleaved so (k=cq, k=cq+4) are adjacent (LDS.64).
    __shared__ u32 Cs[128 * 64];        // 32 KB (reused as Dsm in epilogue)

    const int tid = threadIdx.x;
    const int w   = blockIdx.x * 128 + tid;
    const int wl  = (w < WP - 1) ? w : (WP - 1);
    const int h   = blockIdx.y;
    const int b   = blockIdx.z;

    const float* xb = x   + ((b * 16) * 64 + h) * 512 + wl;
    const float* pb = pts + ((b * 3)  * 64 + h) * 512 + wl;

    // Window center: points[b, d, h+1, w+1]
    const float t0 = pb[512 + 1];
    const float t1 = pb[CH_STRIDE + 512 + 1];
    const float t2 = pb[2 * CH_STRIDE + 512 + 1];
    const u64 ctr0 = pk(t0, t0), ctr1 = pk(t1, t1), ctr2 = pk(t2, t2);

    // ---------------- phase 1: box sums, two channel-half passes ----------------
    #pragma unroll 1
    for (int half = 0; half < 2; ++half) {
        u64 A2[4], Bn[3][4];
        #pragma unroll
        for (int j = 0; j < 4; ++j) { A2[j] = 0ull; Bn[0][j] = 0ull; Bn[1][j] = 0ull; Bn[2][j] = 0ull; }

        #pragma unroll
        for (int r = 0; r < 3; ++r) {
            #pragma unroll
            for (int f = 0; f < 3; ++f) {
                const int off = r * 512 + f;
                float p0 = pb[off];
                float p1 = pb[CH_STRIDE + off];
                float p2 = pb[2 * CH_STRIDE + off];
                u64 q0 = pk(p0, p0), q1 = pk(p1, p1), q2 = pk(p2, p2);
                #pragma unroll
                for (int j = 0; j < 4; ++j) {
                    const int ch = half * 8 + 2 * j;
                    u64 xx = pk(xb[ch * CH_STRIDE + off],
                                xb[(ch + 1) * CH_STRIDE + off]);
                    A2[j]    = add2(A2[j], xx);
                    Bn[0][j] = fma2(q0, xx, Bn[0][j]);
                    Bn[1][j] = fma2(q1, xx, Bn[1][j]);
                    Bn[2][j] = fma2(q2, xx, Bn[2][j]);
                }
            }
        }

        #pragma unroll
        for (int j = 0; j < 4; ++j) {
            const int pr = half * 4 + j;
            u64 C0 = fma2(ctr0, A2[j], neg2(Bn[0][j]));
            u64 C1 = fma2(ctr1, A2[j], neg2(Bn[1][j]));
            u64 C2 = fma2(ctr2, A2[j], neg2(Bn[2][j]));
            float c0l, c0h, c1l, c1h, c2l, c2h, al, ah;
            upk(C0, c0l, c0h); upk(C1, c1l, c1h); upk(C2, c2l, c2h); upk(A2[j], al, ah);

            // interleaved pair layout: [c0l,c0h,c1l,c1h, c2l,c2h,al,ah]
            u32* p = Cs + tid * 64 + ((pr ^ (tid & 7)) << 3);
            *reinterpret_cast<uint4*>(p) =
                make_uint4(tf32r(c0l), tf32r(c0h), tf32r(c1l), tf32r(c1h));
            *reinterpret_cast<uint4*>(p + 4) =
                make_uint4(tf32r(c2l), tf32r(c2h), tf32r(al), tf32r(ah));
        }
    }
    __syncthreads();

    // ---------------- phase 2: out[128px, 32o] = C[128x64] * K^T ----------------
    const int lane  = tid & 31;
    const int wq    = tid >> 5;
    const int g     = lane >> 2;
    const int cq    = lane & 3;
    const int rbase = wq * 32;          // warp's 32-px slab

    float dd[2][4][4];
    #pragma unroll
    for (int mt = 0; mt < 2; ++mt)
        #pragma unroll
        for (int nt = 0; nt < 4; ++nt)
            #pragma unroll
            for (int e = 0; e < 4; ++e) dd[mt][nt][e] = 0.0f;

    #pragma unroll
    for (int kt = 0; kt < 8; ++kt) {
        uint2 bf[4];
        #pragma unroll
        for (int nt = 0; nt < 4; ++nt)
            bf[nt] = *reinterpret_cast<const uint2*>(Kfrag + (nt * 8 + g) * 64 + kt * 8 + 2 * cq);

        #pragma unroll
        for (int mt = 0; mt < 2; ++mt) {
            const int r0 = rbase + mt * 16 + g;            // r0 & 7 == g
            const u32* ap = Cs + r0 * 64 + ((kt ^ g) << 3) + 2 * cq;
            uint2 v0 = *reinterpret_cast<const uint2*>(ap);            // (a0, a2)
            uint2 v1 = *reinterpret_cast<const uint2*>(ap + 8 * 64);   // (a1, a3)
            #pragma unroll
            for (int nt = 0; nt < 4; ++nt)
                mma_tf32(dd[mt][nt][0], dd[mt][nt][1], dd[mt][nt][2], dd[mt][nt][3],
                         v0.x, v1.x, v0.y, v1.y, bf[nt].x, bf[nt].y);
        }
    }
    __syncthreads();   // Cs free -> reuse as Dsm[o][w], stride DSTR

    // scatter D fragments into smem (conflict-free: 8*cq + g distinct per warp)
    #pragma unroll
    for (int mt = 0; mt < 2; ++mt) {
        const int wl0 = rbase + mt * 16 + g;
        #pragma unroll
        for (int nt = 0; nt < 4; ++nt) {
            const int o0 = nt * 8 + 2 * cq;
            Cs[o0 * DSTR + wl0]           = __float_as_uint(dd[mt][nt][0]);
            Cs[(o0 + 1) * DSTR + wl0]     = __float_as_uint(dd[mt][nt][1]);
            Cs[o0 * DSTR + wl0 + 8]       = __float_as_uint(dd[mt][nt][2]);
            Cs[(o0 + 1) * DSTR + wl0 + 8] = __float_as_uint(dd[mt][nt][3]);
        }
    }
    __syncthreads();

    // coalesced stores: warp wq handles o = wq*8 .. wq*8+7, lane covers 4 w's
    const int wb = blockIdx.x * 128 + lane * 4;
    #pragma unroll
    for (int oo = 0; oo < 8; ++oo) {
        const int o = wq * 8 + oo;
        uint4 v = *reinterpret_cast<const uint4*>(Cs + o * DSTR + lane * 4);
        float* p = out + (b * 32 + o) * OUT_PLANE + h * WP + wb;
        // (h*WP + wb) is always even -> float2 aligned; wb max 508 so first pair in-bounds
        *reinterpret_cast<float2*>(p) =
            make_float2(__uint_as_float(v.x), __uint_as_float(v.y));
        if (wb + 2 < WP)
            *reinterpret_cast<float2*>(p + 2) =
                make_float2(__uint_as_float(v.z), __uint_as_float(v.w));
    }
}

extern "C" void kernel_launch(void* const* d_in, const int* in_sizes, int n_in,
                              void* d_out, int out_size)
{
    const float* x = nullptr; const float* kern = nullptr; const float* pts = nullptr;
    for (int i = 0; i < n_in; ++i) {
        if (in_sizes[i] == 8388608)      x    = (const float*)d_in[i];
        else if (in_sizes[i] == 2048)    kern = (const float*)d_in[i];
        else if (in_sizes[i] == 1572864) pts  = (const float*)d_in[i];
    }
    prep_kfrag_kernel<<<8, 256>>>(kern);
    dim3 grid(4, 62, 16);   // 4 w-tiles of 128, 62 h rows, batch
    flex_conv_mma6_kernel<<<grid, 128>>>(x, pts, (float*)d_out);
}

// round 11
// speedup vs baseline: 1.2394x; 1.2394x over previous
#include <cuda_runtime.h>
#include <cstdint>

// x:      (16, 16, 64, 512)  f32
// kernel: (32, 16, 4)        f32
// points: (16, 3, 64, 512)   f32
// out:    (16, 32, 62, 510)  f32
#define CH_STRIDE 32768
#define HP 62
#define WP 510
#define OUT_PLANE (62*510)
#define KSTR 72                 // K smem stride (words): (8g+2cq) banks distinct
#define DSTR 132                // epilogue smem stride (words)

typedef unsigned long long u64;
typedef unsigned int u32;

__device__ __forceinline__ u64 pk(float lo, float hi) {
    u64 r; asm("mov.b64 %0, {%1,%2};" : "=l"(r) : "f"(lo), "f"(hi)); return r;
}
__device__ __forceinline__ void upk(u64 v, float& lo, float& hi) {
    asm("mov.b64 {%0,%1}, %2;" : "=f"(lo), "=f"(hi) : "l"(v));
}
__device__ __forceinline__ u64 fma2(u64 a, u64 b, u64 c) {
    u64 d; asm("fma.rn.f32x2 %0, %1, %2, %3;" : "=l"(d) : "l"(a), "l"(b), "l"(c)); return d;
}
__device__ __forceinline__ u64 add2(u64 a, u64 b) {
    u64 d; asm("add.rn.f32x2 %0, %1, %2;" : "=l"(d) : "l"(a), "l"(b)); return d;
}
__device__ __forceinline__ u64 neg2(u64 a) { return a ^ 0x8000000080000000ULL; }

__device__ __forceinline__ u32 tf32r(float f) {
    u32 r; asm("cvt.rna.tf32.f32 %0, %1;" : "=r"(r) : "f"(f)); return r;
}

__device__ __forceinline__ void mma_tf32(float& d0, float& d1, float& d2, float& d3,
                                         u32 a0, u32 a1, u32 a2, u32 a3,
                                         u32 b0, u32 b1) {
    asm volatile("mma.sync.aligned.m16n8k8.row.col.f32.tf32.tf32.f32 "
                 "{%0,%1,%2,%3}, {%4,%5,%6,%7}, {%8,%9}, {%0,%1,%2,%3};"
                 : "+f"(d0), "+f"(d1), "+f"(d2), "+f"(d3)
                 : "r"(a0), "r"(a1), "r"(a2), "r"(a3), "r"(b0), "r"(b1));
}

__global__ void __launch_bounds__(128, 5)
flex_conv_mma7_kernel(const float* __restrict__ x,
                      const float* __restrict__ kern,
                      const float* __restrict__ pts,
                      float* __restrict__ out)
{
    // C tile: 128 rows x 64 words. 8 groups/row, group idx swizzled pr^(row&7);
    // inside a group, logical word v stored at physical v ^ (4*((row>>2)&1)).
    // Logical order: [C(2pr,0)lo? ...] = channel-lo/hi interleaved so the MMA
    // A-fragment (k=cq, k=cq+4) is one uint2.
    __shared__ u32 Cs[128 * 64];        // 32 KB (reused as Dsm in epilogue)
    __shared__ u32 Ksm[32 * KSTR];      // 9.2 KB, fragment-pair-ordered

    const int tid = threadIdx.x;

    // Stage K: idx = o*64 + c, c = i*4+d; kt = c>>3, cl = c&7,
    // pos = 2*(cl&3) + (cl>>2)  -> (b0,b1) adjacent for LDS.64
    #pragma unroll
    for (int t = 0; t < 16; ++t) {
        int idx = t * 128 + tid;
        int o = idx >> 6, c = idx & 63;
        int pos = 2 * (c & 3) + ((c >> 2) & 1);
        Ksm[o * KSTR + (c >> 3) * 8 + pos] = tf32r(kern[idx]);
    }

    const int w   = blockIdx.x * 128 + tid;
    const int wl  = (w < WP - 1) ? w : (WP - 1);
    const int h   = blockIdx.y;
    const int b   = blockIdx.z;

    const float* xb = x   + ((b * 16) * 64 + h) * 512 + wl;
    const float* pb = pts + ((b * 3)  * 64 + h) * 512 + wl;

    // Window center: points[b, d, h+1, w+1]
    const float t0 = pb[512 + 1];
    const float t1 = pb[CH_STRIDE + 512 + 1];
    const float t2 = pb[2 * CH_STRIDE + 512 + 1];
    const u64 ctr0 = pk(t0, t0), ctr1 = pk(t1, t1), ctr2 = pk(t2, t2);

    const int h2 = (tid >> 2) & 1;      // half-swap selector for C stores

    // ---------------- phase 1: box sums, two channel-half passes ----------------
    #pragma unroll 1
    for (int half = 0; half < 2; ++half) {
        u64 A2[4], Bn[3][4];
        #pragma unroll
        for (int j = 0; j < 4; ++j) { A2[j] = 0ull; Bn[0][j] = 0ull; Bn[1][j] = 0ull; Bn[2][j] = 0ull; }

        #pragma unroll
        for (int r = 0; r < 3; ++r) {
            #pragma unroll
            for (int f = 0; f < 3; ++f) {
                const int off = r * 512 + f;
                float p0 = pb[off];
                float p1 = pb[CH_STRIDE + off];
                float p2 = pb[2 * CH_STRIDE + off];
                u64 q0 = pk(p0, p0), q1 = pk(p1, p1), q2 = pk(p2, p2);
                #pragma unroll
                for (int j = 0; j < 4; ++j) {
                    const int ch = half * 8 + 2 * j;
                    u64 xx = pk(xb[ch * CH_STRIDE + off],
                                xb[(ch + 1) * CH_STRIDE + off]);
                    A2[j]    = add2(A2[j], xx);
                    Bn[0][j] = fma2(q0, xx, Bn[0][j]);
                    Bn[1][j] = fma2(q1, xx, Bn[1][j]);
                    Bn[2][j] = fma2(q2, xx, Bn[2][j]);
                }
            }
        }

        #pragma unroll
        for (int j = 0; j < 4; ++j) {
            const int pr = half * 4 + j;
            u64 C0 = fma2(ctr0, A2[j], neg2(Bn[0][j]));
            u64 C1 = fma2(ctr1, A2[j], neg2(Bn[1][j]));
            u64 C2 = fma2(ctr2, A2[j], neg2(Bn[2][j]));
            float c0l, c0h, c1l, c1h, c2l, c2h, al, ah;
            upk(C0, c0l, c0h); upk(C1, c1l, c1h); upk(C2, c2l, c2h); upk(A2[j], al, ah);

            u32* p = Cs + tid * 64 + ((pr ^ (tid & 7)) << 3);
            uint4 blkA = make_uint4(tf32r(c0l), tf32r(c0h), tf32r(c1l), tf32r(c1h));
            uint4 blkB = make_uint4(tf32r(c2l), tf32r(c2h), tf32r(al), tf32r(ah));
            *reinterpret_cast<uint4*>(p + 4 * h2)       = blkA;
            *reinterpret_cast<uint4*>(p + (4 * h2 ^ 4)) = blkB;
        }
    }
    __syncthreads();

    // ---------------- phase 2: out[128px, 32o] = C[128x64] * K^T ----------------
    const int lane  = tid & 31;
    const int wq    = tid >> 5;
    const int g     = lane >> 2;
    const int cq    = lane & 3;
    const int g2    = (g >> 2) & 1;
    const int rbase = wq * 32;          // warp's 32-px slab

    float dd[2][4][4];
    #pragma unroll
    for (int mt = 0; mt < 2; ++mt)
        #pragma unroll
        for (int nt = 0; nt < 4; ++nt)
            #pragma unroll
            for (int e = 0; e < 4; ++e) dd[mt][nt][e] = 0.0f;

    #pragma unroll
    for (int kt = 0; kt < 8; ++kt) {
        uint2 bf[4];
        #pragma unroll
        for (int nt = 0; nt < 4; ++nt)
            bf[nt] = *reinterpret_cast<const uint2*>(Ksm + (nt * 8 + g) * KSTR + kt * 8 + 2 * cq);

        #pragma unroll
        for (int mt = 0; mt < 2; ++mt) {
            const int r0 = rbase + mt * 16 + g;          // r0&7 == g, (r0>>2)&1 == g2
            const u32* ap = Cs + r0 * 64 + ((kt ^ g) << 3) + ((2 * cq) ^ (4 * g2));
            uint2 v0 = *reinterpret_cast<const uint2*>(ap);            // (a0, a2)
            uint2 v1 = *reinterpret_cast<const uint2*>(ap + 8 * 64);   // (a1, a3)
            #pragma unroll
            for (int nt = 0; nt < 4; ++nt)
                mma_tf32(dd[mt][nt][0], dd[mt][nt][1], dd[mt][nt][2], dd[mt][nt][3],
                         v0.x, v1.x, v0.y, v1.y, bf[nt].x, bf[nt].y);
        }
    }
    __syncthreads();   // Cs free -> reuse as Dsm[o][w], stride DSTR

    // scatter D fragments into smem (banks 8cq+g distinct per instruction)
    #pragma unroll
    for (int mt = 0; mt < 2; ++mt) {
        const int wl0 = rbase + mt * 16 + g;
        #pragma unroll
        for (int nt = 0; nt < 4; ++nt) {
            const int o0 = nt * 8 + 2 * cq;
            Cs[o0 * DSTR + wl0]           = __float_as_uint(dd[mt][nt][0]);
            Cs[(o0 + 1) * DSTR + wl0]     = __float_as_uint(dd[mt][nt][1]);
            Cs[o0 * DSTR + wl0 + 8]       = __float_as_uint(dd[mt][nt][2]);
            Cs[(o0 + 1) * DSTR + wl0 + 8] = __float_as_uint(dd[mt][nt][3]);
        }
    }
    __syncthreads();

    // coalesced stores: warp wq handles o = wq*8 .. wq*8+7, lane covers 4 w's
    const int wb = blockIdx.x * 128 + lane * 4;
    #pragma unroll
    for (int oo = 0; oo < 8; ++oo) {
        const int o = wq * 8 + oo;
        uint4 v = *reinterpret_cast<const uint4*>(Cs + o * DSTR + lane * 4);
        float* p = out + (b * 32 + o) * OUT_PLANE + h * WP + wb;
        // (h*WP + wb) is even -> float2 aligned; wb <= 508 so first pair in-bounds
        *reinterpret_cast<float2*>(p) =
            make_float2(__uint_as_float(v.x), __uint_as_float(v.y));
        if (wb + 2 < WP)
            *reinterpret_cast<float2*>(p + 2) =
                make_float2(__uint_as_float(v.z), __uint_as_float(v.w));
    }
}

extern "C" void kernel_launch(void* const* d_in, const int* in_sizes, int n_in,
                              void* d_out, int out_size)
{
    const float* x = nullptr; const float* kern = nullptr; const float* pts = nullptr;
    for (int i = 0; i < n_in; ++i) {
        if (in_sizes[i] == 8388608)      x    = (const float*)d_in[i];
        else if (in_sizes[i] == 2048)    kern = (const float*)d_in[i];
        else if (in_sizes[i] == 1572864) pts  = (const float*)d_in[i];
    }
    dim3 grid(4, 62, 16);   // 4 w-tiles of 128, 62 h rows, batch
    flex_conv_mma7_kernel<<<grid, 128>>>(x, kern, pts, (float*)d_out);
}